// round 1
// baseline (speedup 1.0000x reference)
#include <cuda_runtime.h>
#include <cuda_bf16.h>
#include <stdint.h>

// Problem constants
#define BATCH 16
#define TT    8192
#define CC    256   // input feature dim
#define HH    256   // hidden dim
#define KW1   7
#define KW2   3

typedef unsigned long long u64;

// ---------------- device scratch (no allocation allowed) ----------------
__device__ float g_h1[(size_t)BATCH * TT * HH];     // conv1 output (B,T,H)
__device__ float g_h2[(size_t)BATCH * TT * HH];     // conv2 output (B,T,H)
__device__ float g_wt1[KW1 * CC * HH];              // transposed weights [k][c][h]
__device__ float g_wt2[KW2 * HH * HH];
__device__ unsigned char g_isb[BATCH * TT];         // boundary flags
__device__ unsigned char g_pad[BATCH * TT];         // normalized padding mask
__device__ int g_start[BATCH * (TT + 1)];           // segment start indices
__device__ int g_nb[BATCH];
__device__ int g_len[BATCH];
__device__ int g_mask_u8;                           // 1 if padding_mask is uint8

// ---------------- f32x2 packed-FMA helpers ----------------
__device__ __forceinline__ u64 pack_dup(float a) {
    u64 d;
    unsigned r = __float_as_uint(a);
    asm("mov.b64 %0, {%1, %2};" : "=l"(d) : "r"(r), "r"(r));
    return d;
}
__device__ __forceinline__ u64 ffma2(u64 a, u64 b, u64 c) {
    u64 d;
    asm("fma.rn.f32x2 %0, %1, %2, %3;" : "=l"(d) : "l"(a), "l"(b), "l"(c));
    return d;
}
__device__ __forceinline__ void unpack2(u64 v, float& lo, float& hi) {
    unsigned l, h;
    asm("mov.b64 {%0, %1}, %2;" : "=r"(l), "=r"(h) : "l"(v));
    lo = __uint_as_float(l);
    hi = __uint_as_float(h);
}

// ---------------- weight transpose: w[h][c][k] -> wt[k][c][h] ----------------
__global__ void transpose_w_kernel(const float* __restrict__ w, float* __restrict__ wt,
                                   int Cout, int Cin, int KW) {
    int i = blockIdx.x * blockDim.x + threadIdx.x;
    int total = Cout * Cin * KW;
    if (i < total) {
        int k = i % KW;
        int rest = i / KW;
        int c = rest % Cin;
        int h = rest / Cin;
        wt[((size_t)k * Cin + c) * Cout + h] = w[i];
    }
}

// ---------------- padding-mask dtype detect + normalize ----------------
__global__ void mask_reset_kernel() { g_mask_u8 = 0; }

__global__ void mask_detect_kernel(const unsigned char* __restrict__ src) {
    // If stored as int32 bools, only bytes at offset %4==0 can be nonzero within
    // the first B*T bytes. If uint8, the (>=T/2) padded tails guarantee nonzero
    // bytes at all offsets mod 4.
    int i = blockIdx.x * blockDim.x + threadIdx.x;
    int found = 0;
    for (int idx = i; idx < BATCH * TT; idx += gridDim.x * blockDim.x) {
        if ((idx & 3) != 0 && src[idx] != 0) found = 1;
    }
    if (__syncthreads_or(found)) {
        if (threadIdx.x == 0) atomicOr(&g_mask_u8, 1);
    }
}

__global__ void mask_normalize_kernel(const unsigned char* __restrict__ src) {
    int i = blockIdx.x * blockDim.x + threadIdx.x;
    if (i < BATCH * TT) {
        if (g_mask_u8)
            g_pad[i] = (src[i] != 0) ? 1 : 0;
        else
            g_pad[i] = (((const int*)src)[i] != 0) ? 1 : 0;
    }
}

// ---------------- conv-as-GEMM kernel (FFMA2 inner loop) ----------------
// Out[b,t,h] = act( bias[h] + sum_k sum_c A[b, t+k-pad, c] * Wt[k][c][h] )
#define BM 128
#define BN 128
#define BKC 16
#define TM 8
#define TN 8

__global__ __launch_bounds__(256, 2)
void conv_gemm_kernel(const float* __restrict__ A, const float* __restrict__ Wt,
                      const float* __restrict__ bias, float* __restrict__ Out,
                      int Cin, int Cout, int KW, int pad, int doRelu) {
    __shared__ float As[BKC][BM + 4];
    __shared__ float Bs[BKC][BN + 4];

    const int b  = blockIdx.z;
    const int t0 = blockIdx.x * BM;
    const int h0 = blockIdx.y * BN;
    const float* Ab = A + (size_t)b * TT * Cin;

    const int tid = threadIdx.x;
    const int tx = tid & 15;          // 0..15 -> column groups
    const int ty = tid >> 4;          // 0..15 -> row groups
    const int m0 = ty * TM;
    const int n0 = tx * TN;

    // A load mapping: 128 rows x 16 cols, float4 along c
    const int arow  = tid >> 2;       // 0..63
    const int acol4 = (tid & 3) * 4;  // 0,4,8,12
    // B load mapping: 16 rows x 128 cols, float4 along h
    const int brow  = tid >> 5;       // 0..7
    const int bcol4 = (tid & 31) * 4; // 0..124

    u64 cc[TM][TN / 2];
#pragma unroll
    for (int r = 0; r < TM; r++)
#pragma unroll
        for (int j = 0; j < TN / 2; j++) cc[r][j] = 0ULL;

    for (int k = 0; k < KW; k++) {
        const int tshift = t0 + k - pad;
        const float* Wk = Wt + (size_t)k * Cin * Cout;
        for (int cb = 0; cb < Cin; cb += BKC) {
            // ---- load A tile (with zero padding at time borders) ----
#pragma unroll
            for (int p = 0; p < 2; p++) {
                int r = arow + p * 64;
                int trow = tshift + r;
                float4 v = make_float4(0.f, 0.f, 0.f, 0.f);
                if (trow >= 0 && trow < TT)
                    v = *(const float4*)&Ab[(size_t)trow * Cin + cb + acol4];
                As[acol4 + 0][r] = v.x;
                As[acol4 + 1][r] = v.y;
                As[acol4 + 2][r] = v.z;
                As[acol4 + 3][r] = v.w;
            }
            // ---- load B tile ----
#pragma unroll
            for (int p = 0; p < 2; p++) {
                int r = brow + p * 8;
                float4 v = *(const float4*)&Wk[(size_t)(cb + r) * Cout + h0 + bcol4];
                *(float4*)&Bs[r][bcol4] = v;
            }
            __syncthreads();

#pragma unroll
            for (int kk = 0; kk < BKC; kk++) {
                float4 a0 = *(const float4*)&As[kk][m0];
                float4 a1 = *(const float4*)&As[kk][m0 + 4];
                ulonglong2 b01 = *(const ulonglong2*)&Bs[kk][n0];
                ulonglong2 b23 = *(const ulonglong2*)&Bs[kk][n0 + 4];
                float av[8];
                av[0] = a0.x; av[1] = a0.y; av[2] = a0.z; av[3] = a0.w;
                av[4] = a1.x; av[5] = a1.y; av[6] = a1.z; av[7] = a1.w;
#pragma unroll
                for (int r = 0; r < TM; r++) {
                    u64 aa = pack_dup(av[r]);
                    cc[r][0] = ffma2(aa, b01.x, cc[r][0]);
                    cc[r][1] = ffma2(aa, b01.y, cc[r][1]);
                    cc[r][2] = ffma2(aa, b23.x, cc[r][2]);
                    cc[r][3] = ffma2(aa, b23.y, cc[r][3]);
                }
            }
            __syncthreads();
        }
    }

    // ---- epilogue: bias + optional relu, coalesced float4 stores ----
    float bz[TN];
#pragma unroll
    for (int j = 0; j < TN; j++) bz[j] = bias[h0 + n0 + j];

#pragma unroll
    for (int r = 0; r < TM; r++) {
        int t = t0 + m0 + r;
        float o[8];
#pragma unroll
        for (int j = 0; j < TN / 2; j++) unpack2(cc[r][j], o[2 * j], o[2 * j + 1]);
#pragma unroll
        for (int j = 0; j < TN; j++) {
            float v = o[j] + bz[j];
            if (doRelu) v = fmaxf(v, 0.f);
            o[j] = v;
        }
        float* op = Out + ((size_t)b * TT + t) * Cout + h0 + n0;
        *(float4*)&op[0] = make_float4(o[0], o[1], o[2], o[3]);
        *(float4*)&op[4] = make_float4(o[4], o[5], o[6], o[7]);
    }
}

// ---------------- conv3 + argmax boundary (warp per token) ----------------
__global__ void boundary_kernel(const float* __restrict__ h2, const float* __restrict__ w3,
                                const float* __restrict__ b3) {
    int gw = (blockIdx.x * blockDim.x + threadIdx.x) >> 5;   // token index (b*T + t)
    int lane = threadIdx.x & 31;
    const float* row = h2 + (size_t)gw * HH;
    float a0 = 0.f, a1 = 0.f;
#pragma unroll
    for (int u = 0; u < 8; u++) {
        int c = lane + 32 * u;
        float hv = row[c];
        a0 += hv * w3[c];
        a1 += hv * w3[HH + c];
    }
#pragma unroll
    for (int off = 16; off; off >>= 1) {
        a0 += __shfl_xor_sync(0xffffffffu, a0, off);
        a1 += __shfl_xor_sync(0xffffffffu, a1, off);
    }
    if (lane == 0) {
        float l0 = a0 + b3[0];
        float l1 = a1 + b3[1];
        // argmax returns 0 on ties -> boundary only if l1 strictly greater
        g_isb[gw] = (l1 > l0 && g_pad[gw] == 0) ? 1 : 0;
    }
}

// ---------------- per-batch scan: segment starts, counts, new_pad ----------------
__global__ void scan_kernel(float* padout, int has_pad_out) {
    __shared__ int s_part[256];
    __shared__ int s_len;
    __shared__ int s_nb;
    const int b = blockIdx.x;
    const int tid = threadIdx.x;
    const unsigned char* ib = g_isb + b * TT;
    const unsigned char* pb = g_pad + b * TT;

    if (tid == 0) s_len = 0;
    __syncthreads();

    const int base = tid * 32;     // 256 threads * 32 = 8192
    int lb = 0, lv = 0;
#pragma unroll 8
    for (int j = 0; j < 32; j++) {
        lb += ib[base + j];
        lv += (pb[base + j] == 0);
    }
    s_part[tid] = lb;
    atomicAdd(&s_len, lv);
    __syncthreads();

    if (tid == 0) {
        int run = 0;
        for (int i = 0; i < 256; i++) { int v = s_part[i]; s_part[i] = run; run += v; }
        s_nb = run;
    }
    __syncthreads();

    int cum = s_part[tid];
    int* gs = g_start + b * (TT + 1);
    for (int j = 0; j < 32; j++) {
        if (ib[base + j]) { cum++; gs[cum] = base + j; }
    }
    const int len = s_len, nb = s_nb;
    if (tid == 0) { gs[0] = 0; g_nb[b] = nb; g_len[b] = len; }

    if (has_pad_out) {
        int nv = (len > 0) ? nb + 1 : 0;
        for (int idx = tid; idx < TT; idx += 256)
            padout[b * TT + idx] = (idx >= nv) ? 1.0f : 0.0f;
    }
}

// ---------------- segment mean pooling (warp per output segment slot) ----------------
__global__ void pool_kernel(const float* __restrict__ x, float* __restrict__ out) {
    int gw = (blockIdx.x * blockDim.x + threadIdx.x) >> 5;  // b*T + s
    int lane = threadIdx.x & 31;
    int b = gw >> 13;      // /8192
    int s = gw & (TT - 1);
    int nb = g_nb[b], len = g_len[b];
    int nv = (len > 0) ? nb + 1 : 0;

    float acc[8];
#pragma unroll
    for (int u = 0; u < 8; u++) acc[u] = 0.f;

    if (s < nv && s < TT) {
        const int* gs = g_start + b * (TT + 1);
        int st = gs[s];
        int en = (s == nb) ? len : gs[s + 1];
        int cnt = en - st;
        if (cnt > 0) {
            const float* xb = x + (((size_t)b * TT + st) << 8);
            for (int t = 0; t < cnt; t++) {
#pragma unroll
                for (int u = 0; u < 8; u++)
                    acc[u] += xb[(size_t)t * CC + lane + 32 * u];
            }
            float fc = (float)cnt;
#pragma unroll
            for (int u = 0; u < 8; u++) acc[u] /= fc;
        }
    }
    float* ob = out + (((size_t)b * TT + s) << 8);
#pragma unroll
    for (int u = 0; u < 8; u++) ob[lane + 32 * u] = acc[u];
}

// ---------------- launch ----------------
extern "C" void kernel_launch(void* const* d_in, const int* in_sizes, int n_in,
                              void* d_out, int out_size) {
    const float* x   = (const float*)d_in[0];
    const unsigned char* pmask = (const unsigned char*)d_in[1];
    const float* w1  = (const float*)d_in[2];
    const float* b1  = (const float*)d_in[3];
    const float* w2  = (const float*)d_in[4];
    const float* b2  = (const float*)d_in[5];
    const float* w3  = (const float*)d_in[6];
    const float* b3  = (const float*)d_in[7];
    float* out = (float*)d_out;

    void *p_h1, *p_h2, *p_wt1, *p_wt2;
    cudaGetSymbolAddress(&p_h1, g_h1);
    cudaGetSymbolAddress(&p_h2, g_h2);
    cudaGetSymbolAddress(&p_wt1, g_wt1);
    cudaGetSymbolAddress(&p_wt2, g_wt2);
    float* h1 = (float*)p_h1;
    float* h2 = (float*)p_h2;
    float* wt1 = (float*)p_wt1;
    float* wt2 = (float*)p_wt2;

    const size_t logits_elems = (size_t)BATCH * TT * CC;
    int has_pad_out = (out_size >= (int)(logits_elems + BATCH * TT)) ? 1 : 0;
    float* padout = out + logits_elems;

    // 0) normalize padding mask (dtype auto-detect)
    mask_reset_kernel<<<1, 1>>>();
    mask_detect_kernel<<<128, 256>>>(pmask);
    mask_normalize_kernel<<<(BATCH * TT + 255) / 256, 256>>>(pmask);

    // 1) transpose weights into [k][c][h]
    transpose_w_kernel<<<(HH * CC * KW1 + 255) / 256, 256>>>(w1, wt1, HH, CC, KW1);
    transpose_w_kernel<<<(HH * HH * KW2 + 255) / 256, 256>>>(w2, wt2, HH, HH, KW2);

    // 2) conv1 + relu : x (B,T,C) -> h1 (B,T,H)
    {
        dim3 grid(TT / BM, HH / BN, BATCH);
        conv_gemm_kernel<<<grid, 256>>>(x, wt1, b1, h1, CC, HH, KW1, KW1 / 2, 1);
    }
    // 3) conv2 + relu : h1 -> h2
    {
        dim3 grid(TT / BM, HH / BN, BATCH);
        conv_gemm_kernel<<<grid, 256>>>(h1, wt2, b2, h2, HH, HH, KW2, 1, 1);
    }
    // 4) conv3 + argmax boundary flags (warp/token)
    boundary_kernel<<<(BATCH * TT) / 8, 256>>>(h2, w3, b3);

    // 5) per-batch scan: starts/counts + new_pad
    scan_kernel<<<BATCH, 256>>>(padout, has_pad_out);

    // 6) segment mean pooling -> new_logits
    pool_kernel<<<(BATCH * TT) / 8, 256>>>(x, out);
}

// round 6
// speedup vs baseline: 1.0719x; 1.0719x over previous
#include <cuda_runtime.h>
#include <cuda_bf16.h>
#include <stdint.h>

// Problem constants
#define BATCH 16
#define TT    8192
#define CC    256
#define HH    256
#define KW1   7
#define KW2   3

#define NELEM ((size_t)BATCH * TT * CC)

typedef __nv_bfloat16 bf16;

// ---------------- device scratch ----------------
__device__ bf16 g_x0[NELEM], g_x1[NELEM], g_x2[NELEM];   // x split
__device__ bf16 g_m0[NELEM], g_m1[NELEM], g_m2[NELEM];   // h1 split
__device__ float g_h2[NELEM];                             // conv2 out fp32
__device__ bf16 g_w1a[KW1 * CC * HH], g_w1b[KW1 * CC * HH], g_w1c[KW1 * CC * HH];
__device__ bf16 g_w2a[KW2 * CC * HH], g_w2b[KW2 * CC * HH], g_w2c[KW2 * CC * HH];
__device__ unsigned char g_isb[BATCH * TT];
__device__ unsigned char g_pad[BATCH * TT];
__device__ int g_start[BATCH * (TT + 1)];
__device__ int g_nb[BATCH];
__device__ int g_len[BATCH];
__device__ int g_mask_u8;

// ---------------- PTX helpers (base compute_103 features only) ----------------
__device__ __forceinline__ uint32_t smem_u32(const void* p) {
    uint32_t a;
    asm("{ .reg .u64 t; cvta.to.shared.u64 t, %1; cvt.u32.u64 %0, t; }" : "=r"(a) : "l"(p));
    return a;
}
__device__ __forceinline__ void cp_async16(uint32_t dst, const void* src, int srcsize) {
    asm volatile("cp.async.cg.shared.global [%0], [%1], 16, %2;"
                 :: "r"(dst), "l"(src), "r"(srcsize) : "memory");
}
__device__ __forceinline__ void cp_commit() {
    asm volatile("cp.async.commit_group;" ::: "memory");
}
template<int N>
__device__ __forceinline__ void cp_wait() {
    asm volatile("cp.async.wait_group %0;" :: "n"(N) : "memory");
}
__device__ __forceinline__ void ldsm_x4(uint32_t (&r)[4], uint32_t addr) {
    asm volatile("ldmatrix.sync.aligned.m8n8.x4.shared.b16 {%0,%1,%2,%3}, [%4];"
                 : "=r"(r[0]), "=r"(r[1]), "=r"(r[2]), "=r"(r[3]) : "r"(addr));
}
__device__ __forceinline__ void ldsm_x4_t(uint32_t (&r)[4], uint32_t addr) {
    asm volatile("ldmatrix.sync.aligned.m8n8.x4.trans.shared.b16 {%0,%1,%2,%3}, [%4];"
                 : "=r"(r[0]), "=r"(r[1]), "=r"(r[2]), "=r"(r[3]) : "r"(addr));
}
__device__ __forceinline__ void mma16816(float (&c)[4], const uint32_t (&a)[4],
                                         uint32_t b0, uint32_t b1) {
    asm volatile("mma.sync.aligned.m16n8k16.row.col.f32.bf16.bf16.f32 "
                 "{%0,%1,%2,%3},{%4,%5,%6,%7},{%8,%9},{%0,%1,%2,%3};"
                 : "+f"(c[0]), "+f"(c[1]), "+f"(c[2]), "+f"(c[3])
                 : "r"(a[0]), "r"(a[1]), "r"(a[2]), "r"(a[3]), "r"(b0), "r"(b1));
}

// ---------------- fp32 -> 3x bf16 split ----------------
__device__ __forceinline__ void split3(float f, bf16& b0, bf16& b1, bf16& b2) {
    b0 = __float2bfloat16_rn(f);
    float r = f - __bfloat162float(b0);
    b1 = __float2bfloat16_rn(r);
    float r2 = r - __bfloat162float(b1);
    b2 = __float2bfloat16_rn(r2);
}
__device__ __forceinline__ unsigned pack2(bf16 a, bf16 b) {
    return (unsigned)__bfloat16_as_ushort(a) | ((unsigned)__bfloat16_as_ushort(b) << 16);
}

// ---------------- mask dtype detect + normalize ----------------
__global__ void mask_reset_kernel() { g_mask_u8 = 0; }
__global__ void mask_detect_kernel(const unsigned char* __restrict__ src) {
    int i = blockIdx.x * blockDim.x + threadIdx.x;
    int found = 0;
    for (int idx = i; idx < BATCH * TT; idx += gridDim.x * blockDim.x)
        if ((idx & 3) != 0 && src[idx] != 0) found = 1;
    if (__syncthreads_or(found))
        if (threadIdx.x == 0) atomicOr(&g_mask_u8, 1);
}
__global__ void mask_normalize_kernel(const unsigned char* __restrict__ src) {
    int i = blockIdx.x * blockDim.x + threadIdx.x;
    if (i < BATCH * TT) {
        if (g_mask_u8) g_pad[i] = (src[i] != 0) ? 1 : 0;
        else           g_pad[i] = (((const int*)src)[i] != 0) ? 1 : 0;
    }
}

// ---------------- input split + weight prepack ----------------
__global__ void split_x_kernel(const float* __restrict__ x, bf16* o0, bf16* o1, bf16* o2, int n) {
    int i = blockIdx.x * blockDim.x + threadIdx.x;
    if (i < n) {
        bf16 b0, b1, b2;
        split3(x[i], b0, b1, b2);
        o0[i] = b0; o1[i] = b1; o2[i] = b2;
    }
}
// w[h][c][k] (torch OIW) -> wt[k][c][h], 3 bf16 planes
__global__ void prepack_w_kernel(const float* __restrict__ w, bf16* o0, bf16* o1, bf16* o2, int KW) {
    int i = blockIdx.x * blockDim.x + threadIdx.x;
    int total = 256 * 256 * KW;
    if (i < total) {
        int k = i % KW;
        int rest = i / KW;
        int c = rest % 256;
        int h = rest / 256;
        bf16 b0, b1, b2;
        split3(w[i], b0, b1, b2);
        size_t o = (((size_t)k * 256 + c) << 8) + h;
        o0[o] = b0; o1[o] = b1; o2[o] = b2;
    }
}

// ---------------- HMMA conv kernel ----------------
// D[t,h] = sum_kw sum_c A[t+kw-PAD, c] * Wt[kw][c][h], bf16x3 pairs (6 products).
// CTA tile M=128 (t) x N=128 (h); K-chunks of 16 c; 8 warps = 4m x 2n (warp 32x64).
static constexpr int A_PL = 128 * 48;            // plane: 128 rows x 24 bf16 (48B, 32B data)
static constexpr int B_PL = 16 * 272;            // plane: 16 rows x 136 bf16 (272B, 256B data)
static constexpr int ST_B_OFF = 3 * A_PL;        // 18432
static constexpr int STAGE_BYTES = 3 * A_PL + 3 * B_PL;  // 31488
static constexpr int STAGES = 3;
static constexpr int SMEM_BYTES = STAGES * STAGE_BYTES;  // 94464

template<int KW, int PAD, int SPLIT_OUT>
__global__ void __launch_bounds__(256, 1)
conv_mma(const bf16* __restrict__ A0, const bf16* __restrict__ A1, const bf16* __restrict__ A2,
         const bf16* __restrict__ W0, const bf16* __restrict__ W1, const bf16* __restrict__ W2,
         const float* __restrict__ bias,
         bf16* __restrict__ O0, bf16* __restrict__ O1, bf16* __restrict__ O2,
         float* __restrict__ OF) {
    extern __shared__ char smem[];
    const uint32_t sb = smem_u32(smem);
    const int tid = threadIdx.x;
    const int lane = tid & 31;
    const int wid = tid >> 5;
    const int h0 = blockIdx.x * 128;        // h fastest -> A reuse in L2 across h-tiles
    const int t0 = blockIdx.y * 128;
    const int bz = blockIdx.z;
    const int m0w = (wid & 3) * 32;
    const int n0w = (wid >> 2) * 64;
    constexpr int NC = KW * 16;

    auto load_stage = [&](int s, int ci) {
        const int kw = ci >> 4;
        const int cb0 = (ci & 15) << 4;
        const uint32_t stg = sb + s * STAGE_BYTES;
        // A: 3 planes x 128 rows x 2 chunks of 16B  (768 cp.async)
#pragma unroll
        for (int j = 0; j < 3; j++) {
            int idx = tid + j * 256;
            int p = idx >> 8, rem = idx & 255;
            int row = rem >> 1, cb = rem & 1;
            const bf16* srcb = (p == 0) ? A0 : ((p == 1) ? A1 : A2);
            int trow = t0 + kw - PAD + row;
            int ok = ((unsigned)trow < (unsigned)TT) ? 16 : 0;
            const void* src = srcb + (((size_t)(bz * TT + (ok ? trow : 0))) << 8) + cb0 + cb * 8;
            cp_async16(stg + p * A_PL + row * 48 + cb * 16, src, ok);
        }
        // B: 3 planes x 16 rows x 16 chunks of 16B  (768 cp.async) -- FULL 128 h cols
#pragma unroll
        for (int j = 0; j < 3; j++) {
            int idx = tid + j * 256;
            int p = idx >> 8, rem = idx & 255;
            int row = rem >> 4, cb = rem & 15;
            const bf16* wsrc = (p == 0) ? W0 : ((p == 1) ? W1 : W2);
            const void* src = wsrc + (((size_t)(kw * 256 + cb0 + row)) << 8) + h0 + cb * 8;
            cp_async16(stg + ST_B_OFF + p * B_PL + row * 272 + cb * 16, src, 16);
        }
        cp_commit();
    };

    float acc[2][8][4];
#pragma unroll
    for (int mt = 0; mt < 2; mt++)
#pragma unroll
        for (int nt = 0; nt < 8; nt++)
#pragma unroll
            for (int e = 0; e < 4; e++) acc[mt][nt][e] = 0.f;

    // prologue: stages 0..STAGES-2
    load_stage(0, 0);
    load_stage(1, 1);

    // per-lane ldmatrix address components
    const int arow = lane & 15, acb = lane >> 4;            // A x4
    const int brow = ((lane >> 3) & 1) * 8 + (lane & 7);    // B x4.trans row (k/c)
    const int bno = (lane >> 4) * 8;                        // B n sub-offset

    for (int ci = 0; ci < NC; ci++) {
        cp_wait<STAGES - 2>();
        __syncthreads();
        if (ci + STAGES - 1 < NC) load_stage((ci + STAGES - 1) % STAGES, ci + STAGES - 1);

        const uint32_t stg = sb + (ci % STAGES) * STAGE_BYTES;

        uint32_t af[3][2][4];
#pragma unroll
        for (int p = 0; p < 3; p++)
#pragma unroll
            for (int mt = 0; mt < 2; mt++)
                ldsm_x4(af[p][mt], stg + p * A_PL + (m0w + mt * 16 + arow) * 48 + acb * 16);

        uint32_t bfr[3][4][4];
#pragma unroll
        for (int p = 0; p < 3; p++)
#pragma unroll
            for (int ng = 0; ng < 4; ng++)
                ldsm_x4_t(bfr[p][ng], stg + ST_B_OFF + p * B_PL + brow * 272 +
                                      (n0w + ng * 16 + bno) * 2);

        const int PA[6] = {0, 0, 1, 1, 0, 2};
        const int PB[6] = {0, 1, 0, 1, 2, 0};
#pragma unroll
        for (int q = 0; q < 6; q++) {
            const int pa = PA[q], pb = PB[q];
#pragma unroll
            for (int mt = 0; mt < 2; mt++)
#pragma unroll
                for (int nt = 0; nt < 8; nt++)
                    mma16816(acc[mt][nt], af[pa][mt],
                             bfr[pb][nt >> 1][(nt & 1) * 2],
                             bfr[pb][nt >> 1][(nt & 1) * 2 + 1]);
        }
        __syncthreads();
    }

    // ---- epilogue: bias + relu; split3->bf16 planes or fp32 ----
    const int g = lane >> 2, col = (lane & 3) * 2;
#pragma unroll
    for (int mt = 0; mt < 2; mt++) {
#pragma unroll
        for (int half = 0; half < 2; half++) {
            const int t = t0 + m0w + mt * 16 + g + half * 8;
            const size_t rowoff = ((size_t)(bz * TT + t)) << 8;
#pragma unroll
            for (int nt = 0; nt < 8; nt++) {
                const int h = h0 + n0w + nt * 8 + col;
                float v0 = acc[mt][nt][half * 2]     + __ldg(&bias[h]);
                float v1 = acc[mt][nt][half * 2 + 1] + __ldg(&bias[h + 1]);
                v0 = fmaxf(v0, 0.f);
                v1 = fmaxf(v1, 0.f);
                if (SPLIT_OUT) {
                    bf16 a0, a1, a2, c0, c1, c2;
                    split3(v0, a0, a1, a2);
                    split3(v1, c0, c1, c2);
                    *(uint32_t*)(O0 + rowoff + h) = pack2(a0, c0);
                    *(uint32_t*)(O1 + rowoff + h) = pack2(a1, c1);
                    *(uint32_t*)(O2 + rowoff + h) = pack2(a2, c2);
                } else {
                    *(float2*)(OF + rowoff + h) = make_float2(v0, v1);
                }
            }
        }
    }
}

// ---------------- conv3 + argmax boundary (warp per token) ----------------
__global__ void boundary_kernel(const float* __restrict__ h2, const float* __restrict__ w3,
                                const float* __restrict__ b3) {
    int gw = (blockIdx.x * blockDim.x + threadIdx.x) >> 5;
    int lane = threadIdx.x & 31;
    const float* row = h2 + (size_t)gw * HH;
    float a0 = 0.f, a1 = 0.f;
#pragma unroll
    for (int u = 0; u < 8; u++) {
        int c = lane + 32 * u;
        float hv = row[c];
        a0 += hv * w3[c];
        a1 += hv * w3[HH + c];
    }
#pragma unroll
    for (int off = 16; off; off >>= 1) {
        a0 += __shfl_xor_sync(0xffffffffu, a0, off);
        a1 += __shfl_xor_sync(0xffffffffu, a1, off);
    }
    if (lane == 0) {
        float l0 = a0 + b3[0];
        float l1 = a1 + b3[1];
        g_isb[gw] = (l1 > l0 && g_pad[gw] == 0) ? 1 : 0;
    }
}

// ---------------- per-batch scan ----------------
__global__ void scan_kernel(float* padout, int has_pad_out) {
    __shared__ int s_part[256];
    __shared__ int s_len;
    __shared__ int s_nb;
    const int b = blockIdx.x;
    const int tid = threadIdx.x;
    const unsigned char* ib = g_isb + b * TT;
    const unsigned char* pb = g_pad + b * TT;

    if (tid == 0) s_len = 0;
    __syncthreads();

    const int base = tid * 32;
    int lb = 0, lv = 0;
#pragma unroll 8
    for (int j = 0; j < 32; j++) {
        lb += ib[base + j];
        lv += (pb[base + j] == 0);
    }
    s_part[tid] = lb;
    atomicAdd(&s_len, lv);
    __syncthreads();

    if (tid == 0) {
        int run = 0;
        for (int i = 0; i < 256; i++) { int v = s_part[i]; s_part[i] = run; run += v; }
        s_nb = run;
    }
    __syncthreads();

    int cum = s_part[tid];
    int* gs = g_start + b * (TT + 1);
    for (int j = 0; j < 32; j++) {
        if (ib[base + j]) { cum++; gs[cum] = base + j; }
    }
    const int len = s_len, nb = s_nb;
    if (tid == 0) { gs[0] = 0; g_nb[b] = nb; g_len[b] = len; }

    if (has_pad_out) {
        int nv = (len > 0) ? nb + 1 : 0;
        for (int idx = tid; idx < TT; idx += 256)
            padout[b * TT + idx] = (idx >= nv) ? 1.0f : 0.0f;
    }
}

// ---------------- segment mean pooling (warp per segment slot) ----------------
__global__ void pool_kernel(const float* __restrict__ x, float* __restrict__ out) {
    int gw = (blockIdx.x * blockDim.x + threadIdx.x) >> 5;
    int lane = threadIdx.x & 31;
    int b = gw >> 13;
    int s = gw & (TT - 1);
    int nb = g_nb[b], len = g_len[b];
    int nv = (len > 0) ? nb + 1 : 0;

    float acc[8];
#pragma unroll
    for (int u = 0; u < 8; u++) acc[u] = 0.f;

    if (s < nv && s < TT) {
        const int* gs = g_start + b * (TT + 1);
        int st = gs[s];
        int en = (s == nb) ? len : gs[s + 1];
        int cnt = en - st;
        if (cnt > 0) {
            const float* xb = x + (((size_t)b * TT + st) << 8);
            for (int t = 0; t < cnt; t++) {
#pragma unroll
                for (int u = 0; u < 8; u++)
                    acc[u] += xb[(size_t)t * CC + lane + 32 * u];
            }
            float fc = (float)cnt;
#pragma unroll
            for (int u = 0; u < 8; u++) acc[u] /= fc;
        }
    }
    float* ob = out + (((size_t)b * TT + s) << 8);
#pragma unroll
    for (int u = 0; u < 8; u++) ob[lane + 32 * u] = acc[u];
}

// ---------------- launch ----------------
extern "C" void kernel_launch(void* const* d_in, const int* in_sizes, int n_in,
                              void* d_out, int out_size) {
    const float* x = (const float*)d_in[0];
    const unsigned char* pmask = (const unsigned char*)d_in[1];
    const float* w1 = (const float*)d_in[2];
    const float* b1 = (const float*)d_in[3];
    const float* w2 = (const float*)d_in[4];
    const float* b2 = (const float*)d_in[5];
    const float* w3 = (const float*)d_in[6];
    const float* b3 = (const float*)d_in[7];
    float* out = (float*)d_out;

    auto sym = [](const void* s) { void* p; cudaGetSymbolAddress(&p, s); return p; };
    bf16* x0 = (bf16*)sym(g_x0);
    bf16* x1 = (bf16*)sym(g_x1);
    bf16* x2 = (bf16*)sym(g_x2);
    bf16* m0 = (bf16*)sym(g_m0);
    bf16* m1 = (bf16*)sym(g_m1);
    bf16* m2 = (bf16*)sym(g_m2);
    float* h2 = (float*)sym(g_h2);
    bf16* w1a = (bf16*)sym(g_w1a);
    bf16* w1b = (bf16*)sym(g_w1b);
    bf16* w1c = (bf16*)sym(g_w1c);
    bf16* w2a = (bf16*)sym(g_w2a);
    bf16* w2b = (bf16*)sym(g_w2b);
    bf16* w2c = (bf16*)sym(g_w2c);

    const size_t logits_elems = (size_t)BATCH * TT * CC;
    int has_pad_out = (out_size >= (int)(logits_elems + BATCH * TT)) ? 1 : 0;
    float* padout = out + logits_elems;

    cudaFuncSetAttribute(conv_mma<KW1, KW1 / 2, 1>,
                         cudaFuncAttributeMaxDynamicSharedMemorySize, SMEM_BYTES);
    cudaFuncSetAttribute(conv_mma<KW2, 1, 0>,
                         cudaFuncAttributeMaxDynamicSharedMemorySize, SMEM_BYTES);

    // 0) padding mask normalize
    mask_reset_kernel<<<1, 1>>>();
    mask_detect_kernel<<<128, 256>>>(pmask);
    mask_normalize_kernel<<<(BATCH * TT + 255) / 256, 256>>>(pmask);

    // 1) weight prepack: w[h][c][k] -> wt[k][c][h], 3 bf16 planes
    prepack_w_kernel<<<(256 * 256 * KW1 + 255) / 256, 256>>>(w1, w1a, w1b, w1c, KW1);
    prepack_w_kernel<<<(256 * 256 * KW2 + 255) / 256, 256>>>(w2, w2a, w2b, w2c, KW2);

    // 2) split x into 3 bf16 planes
    split_x_kernel<<<(int)((NELEM + 255) / 256), 256>>>(x, x0, x1, x2, (int)NELEM);

    // 3) conv1 + relu -> h1 (bf16x3 planes)
    {
        dim3 grid(HH / 128, TT / 128, BATCH);
        conv_mma<KW1, KW1 / 2, 1><<<grid, 256, SMEM_BYTES>>>(
            x0, x1, x2, w1a, w1b, w1c, b1, m0, m1, m2, nullptr);
    }
    // 4) conv2 + relu -> h2 (fp32)
    {
        dim3 grid(HH / 128, TT / 128, BATCH);
        conv_mma<KW2, 1, 0><<<grid, 256, SMEM_BYTES>>>(
            m0, m1, m2, w2a, w2b, w2c, b2, nullptr, nullptr, nullptr, h2);
    }
    // 5) conv3 + argmax boundary flags
    boundary_kernel<<<(BATCH * TT) / 8, 256>>>(h2, w3, b3);
    // 6) per-batch scan
    scan_kernel<<<BATCH, 256>>>(padout, has_pad_out);
    // 7) segment mean pooling
    pool_kernel<<<(BATCH * TT) / 8, 256>>>(x, out);
}

// round 8
// speedup vs baseline: 1.7519x; 1.6343x over previous
#include <cuda_runtime.h>
#include <cuda_fp16.h>
#include <cuda_bf16.h>
#include <stdint.h>

// Problem constants
#define BATCH 16
#define TT    8192
#define CC    256
#define HH    256
#define KW1   7
#define KW2   3

#define NELEM ((size_t)BATCH * TT * CC)

// Weight pre-scale (exact power of two; epilogue multiplies by inverse)
#define WSCALE 4096.0f
#define WSCALE_INV (1.0f / 4096.0f)

// ---------------- device scratch ----------------
__device__ __half g_x0[NELEM], g_x1[NELEM];     // x split (2 fp16 planes)
__device__ __half g_m0[NELEM], g_m1[NELEM];     // h1 split (2 fp16 planes)
__device__ __half g_w1a[KW1 * CC * HH], g_w1b[KW1 * CC * HH];
__device__ __half g_w2a[KW2 * CC * HH], g_w2b[KW2 * CC * HH];
__device__ float g_logit[BATCH * TT * 2];       // fused conv3 partial logits
__device__ unsigned char g_isb[BATCH * TT];
__device__ unsigned char g_pad[BATCH * TT];
__device__ int g_start[BATCH * (TT + 1)];
__device__ int g_nb[BATCH];
__device__ int g_len[BATCH];
__device__ int g_mask_u8;

// ---------------- PTX helpers ----------------
__device__ __forceinline__ uint32_t smem_u32(const void* p) {
    uint32_t a;
    asm("{ .reg .u64 t; cvta.to.shared.u64 t, %1; cvt.u32.u64 %0, t; }" : "=r"(a) : "l"(p));
    return a;
}
__device__ __forceinline__ void cp_async16(uint32_t dst, const void* src, int srcsize) {
    asm volatile("cp.async.cg.shared.global [%0], [%1], 16, %2;"
                 :: "r"(dst), "l"(src), "r"(srcsize) : "memory");
}
__device__ __forceinline__ void cp_commit() {
    asm volatile("cp.async.commit_group;" ::: "memory");
}
template<int N>
__device__ __forceinline__ void cp_wait() {
    asm volatile("cp.async.wait_group %0;" :: "n"(N) : "memory");
}
__device__ __forceinline__ void ldsm_x4(uint32_t (&r)[4], uint32_t addr) {
    asm volatile("ldmatrix.sync.aligned.m8n8.x4.shared.b16 {%0,%1,%2,%3}, [%4];"
                 : "=r"(r[0]), "=r"(r[1]), "=r"(r[2]), "=r"(r[3]) : "r"(addr));
}
__device__ __forceinline__ void ldsm_x4_t(uint32_t (&r)[4], uint32_t addr) {
    asm volatile("ldmatrix.sync.aligned.m8n8.x4.trans.shared.b16 {%0,%1,%2,%3}, [%4];"
                 : "=r"(r[0]), "=r"(r[1]), "=r"(r[2]), "=r"(r[3]) : "r"(addr));
}
__device__ __forceinline__ void mma16816(float (&c)[4], const uint32_t (&a)[4],
                                         uint32_t b0, uint32_t b1) {
    asm volatile("mma.sync.aligned.m16n8k16.row.col.f32.f16.f16.f32 "
                 "{%0,%1,%2,%3},{%4,%5,%6,%7},{%8,%9},{%0,%1,%2,%3};"
                 : "+f"(c[0]), "+f"(c[1]), "+f"(c[2]), "+f"(c[3])
                 : "r"(a[0]), "r"(a[1]), "r"(a[2]), "r"(a[3]), "r"(b0), "r"(b1));
}

// ---------------- fp32 -> 2x fp16 split ----------------
__device__ __forceinline__ void split2h(float f, __half& h0, __half& h1) {
    h0 = __float2half_rn(f);
    float r = f - __half2float(h0);
    h1 = __float2half_rn(r);
}
__device__ __forceinline__ unsigned pack2h(__half a, __half b) {
    return (unsigned)__half_as_ushort(a) | ((unsigned)__half_as_ushort(b) << 16);
}

// ---------------- mask dtype detect + normalize ----------------
__global__ void mask_reset_kernel() { g_mask_u8 = 0; }
__global__ void mask_detect_kernel(const unsigned char* __restrict__ src) {
    int i = blockIdx.x * blockDim.x + threadIdx.x;
    int found = 0;
    for (int idx = i; idx < BATCH * TT; idx += gridDim.x * blockDim.x)
        if ((idx & 3) != 0 && src[idx] != 0) found = 1;
    if (__syncthreads_or(found))
        if (threadIdx.x == 0) atomicOr(&g_mask_u8, 1);
}
__global__ void mask_normalize_kernel(const unsigned char* __restrict__ src) {
    int i = blockIdx.x * blockDim.x + threadIdx.x;
    if (i < BATCH * TT) {
        if (g_mask_u8) g_pad[i] = (src[i] != 0) ? 1 : 0;
        else           g_pad[i] = (((const int*)src)[i] != 0) ? 1 : 0;
    }
}

// ---------------- input split + weight prepack ----------------
__global__ void split_x_kernel(const float* __restrict__ x, __half* o0, __half* o1, int n) {
    int i = blockIdx.x * blockDim.x + threadIdx.x;
    if (i < n) {
        __half h0, h1;
        split2h(x[i], h0, h1);
        o0[i] = h0; o1[i] = h1;
    }
}
// w[h][c][k] (torch OIW) -> wt[k][c][h] * WSCALE, 2 fp16 planes
__global__ void prepack_w_kernel(const float* __restrict__ w, __half* o0, __half* o1, int KW) {
    int i = blockIdx.x * blockDim.x + threadIdx.x;
    int total = 256 * 256 * KW;
    if (i < total) {
        int k = i % KW;
        int rest = i / KW;
        int c = rest % 256;
        int h = rest / 256;
        __half h0, h1;
        split2h(w[i] * WSCALE, h0, h1);
        size_t o = (((size_t)k * 256 + c) << 8) + h;
        o0[o] = h0; o1[o] = h1;
    }
}

__global__ void zero_logits_kernel() {
    int i = blockIdx.x * blockDim.x + threadIdx.x;
    if (i < BATCH * TT * 2) g_logit[i] = 0.f;
}

// ---------------- HMMA conv kernel (fp16 split-2, 3 products) ----------------
// D[t,h] = (1/WSCALE) * sum_kw sum_c A[t+kw-PAD, c] * Wt[kw][c][h]   (+bias, relu)
// CTA tile M=128 (t) x N=128 (h); K-chunks of 16 c; 8 warps = 4m x 2n (warp 32x64).
static constexpr int A_PL = 128 * 48;            // plane: 128 rows x 48B (32B data + pad)
static constexpr int B_PL = 16 * 272;            // plane: 16 rows x 272B (256B data + pad)
static constexpr int ST_B_OFF = 2 * A_PL;        // 12288
static constexpr int STAGE_BYTES = 2 * A_PL + 2 * B_PL;  // 20992
static constexpr int STAGES = 4;
static constexpr int SMEM_BYTES = STAGES * STAGE_BYTES;  // 83968

template<int KW, int PAD, int SPLIT_OUT>
__global__ void __launch_bounds__(256, 1)
conv_mma(const __half* __restrict__ A0, const __half* __restrict__ A1,
         const __half* __restrict__ W0, const __half* __restrict__ W1,
         const float* __restrict__ bias,
         __half* __restrict__ O0, __half* __restrict__ O1,
         float* __restrict__ LG, const float* __restrict__ w3) {
    extern __shared__ char smem[];
    const uint32_t sb = smem_u32(smem);
    const int tid = threadIdx.x;
    const int lane = tid & 31;
    const int wid = tid >> 5;
    const int h0 = blockIdx.x * 128;
    const int t0 = blockIdx.y * 128;
    const int bz = blockIdx.z;
    const int m0w = (wid & 3) * 32;
    const int n0w = (wid >> 2) * 64;
    constexpr int NC = KW * 16;

    auto load_stage = [&](int s, int ci) {
        const int kw = ci >> 4;
        const int cb0 = (ci & 15) << 4;
        const uint32_t stg = sb + s * STAGE_BYTES;
        // A: 2 planes x 128 rows x 2 chunks of 16B (512 cp.async)
#pragma unroll
        for (int j = 0; j < 2; j++) {
            int idx = tid + j * 256;
            int p = idx >> 8, rem = idx & 255;
            int row = rem >> 1, cb = rem & 1;
            const __half* srcb = (p == 0) ? A0 : A1;
            int trow = t0 + kw - PAD + row;
            int ok = ((unsigned)trow < (unsigned)TT) ? 16 : 0;
            const void* src = srcb + (((size_t)(bz * TT + (ok ? trow : 0))) << 8) + cb0 + cb * 8;
            cp_async16(stg + p * A_PL + row * 48 + cb * 16, src, ok);
        }
        // B: 2 planes x 16 rows x 16 chunks of 16B (512 cp.async)
#pragma unroll
        for (int j = 0; j < 2; j++) {
            int idx = tid + j * 256;
            int p = idx >> 8, rem = idx & 255;
            int row = rem >> 4, cb = rem & 15;
            const __half* wsrc = (p == 0) ? W0 : W1;
            const void* src = wsrc + (((size_t)(kw * 256 + cb0 + row)) << 8) + h0 + cb * 8;
            cp_async16(stg + ST_B_OFF + p * B_PL + row * 272 + cb * 16, src, 16);
        }
        cp_commit();
    };

    float acc[2][8][4];
#pragma unroll
    for (int mt = 0; mt < 2; mt++)
#pragma unroll
        for (int nt = 0; nt < 8; nt++)
#pragma unroll
            for (int e = 0; e < 4; e++) acc[mt][nt][e] = 0.f;

    // prologue: fill STAGES-1 stages
    load_stage(0, 0);
    load_stage(1, 1);
    load_stage(2, 2);

    const int arow = lane & 15, acb = lane >> 4;            // A ldmatrix x4
    const int brow = ((lane >> 3) & 1) * 8 + (lane & 7);    // B ldmatrix x4.trans (c-row)
    const int bno = (lane >> 4) * 8;                        // B n sub-offset

    for (int ci = 0; ci < NC; ci++) {
        cp_wait<STAGES - 2>();
        __syncthreads();
        if (ci + STAGES - 1 < NC) load_stage((ci + STAGES - 1) % STAGES, ci + STAGES - 1);

        const uint32_t stg = sb + (ci % STAGES) * STAGE_BYTES;

        uint32_t af[2][2][4];
#pragma unroll
        for (int p = 0; p < 2; p++)
#pragma unroll
            for (int mt = 0; mt < 2; mt++)
                ldsm_x4(af[p][mt], stg + p * A_PL + (m0w + mt * 16 + arow) * 48 + acb * 16);

        uint32_t bfr[2][4][4];
#pragma unroll
        for (int p = 0; p < 2; p++)
#pragma unroll
            for (int ng = 0; ng < 4; ng++)
                ldsm_x4_t(bfr[p][ng], stg + ST_B_OFF + p * B_PL + brow * 272 +
                                      (n0w + ng * 16 + bno) * 2);

        // 3 products: a0*b0, a0*b1, a1*b0
        const int PA[3] = {0, 0, 1};
        const int PB[3] = {0, 1, 0};
#pragma unroll
        for (int q = 0; q < 3; q++) {
            const int pa = PA[q], pb = PB[q];
#pragma unroll
            for (int mt = 0; mt < 2; mt++)
#pragma unroll
                for (int nt = 0; nt < 8; nt++)
                    mma16816(acc[mt][nt], af[pa][mt],
                             bfr[pb][nt >> 1][(nt & 1) * 2],
                             bfr[pb][nt >> 1][(nt & 1) * 2 + 1]);
        }
        __syncthreads();
    }

    // ---- epilogue ----
    const int g = lane >> 2, col = (lane & 3) * 2;
#pragma unroll
    for (int mt = 0; mt < 2; mt++) {
#pragma unroll
        for (int half = 0; half < 2; half++) {
            const int t = t0 + m0w + mt * 16 + g + half * 8;
            const size_t rowoff = ((size_t)(bz * TT + t)) << 8;
            float s0 = 0.f, s1 = 0.f;
#pragma unroll
            for (int nt = 0; nt < 8; nt++) {
                const int h = h0 + n0w + nt * 8 + col;
                float v0 = acc[mt][nt][half * 2]     * WSCALE_INV + __ldg(&bias[h]);
                float v1 = acc[mt][nt][half * 2 + 1] * WSCALE_INV + __ldg(&bias[h + 1]);
                v0 = fmaxf(v0, 0.f);
                v1 = fmaxf(v1, 0.f);
                if (SPLIT_OUT) {
                    __half a0, a1, c0, c1;
                    split2h(v0, a0, a1);
                    split2h(v1, c0, c1);
                    *(uint32_t*)(O0 + rowoff + h) = pack2h(a0, c0);
                    *(uint32_t*)(O1 + rowoff + h) = pack2h(a1, c1);
                } else {
                    // fused conv3: partial logits over this thread's h columns
                    s0 += v0 * __ldg(&w3[h])      + v1 * __ldg(&w3[h + 1]);
                    s1 += v0 * __ldg(&w3[HH + h]) + v1 * __ldg(&w3[HH + h + 1]);
                }
            }
            if (!SPLIT_OUT) {
                float* lg = LG + ((size_t)(bz * TT + t)) * 2;
                atomicAdd(lg, s0);
                atomicAdd(lg + 1, s1);
            }
        }
    }
}

// ---------------- boundary decision from fused logits ----------------
__global__ void boundary_kernel(const float* __restrict__ b3) {
    int i = blockIdx.x * blockDim.x + threadIdx.x;
    if (i < BATCH * TT) {
        float l0 = g_logit[2 * i]     + b3[0];
        float l1 = g_logit[2 * i + 1] + b3[1];
        g_isb[i] = (l1 > l0 && g_pad[i] == 0) ? 1 : 0;
    }
}

// ---------------- per-batch scan ----------------
__global__ void scan_kernel(float* padout, int has_pad_out) {
    __shared__ int s_part[256];
    __shared__ int s_len;
    __shared__ int s_nb;
    const int b = blockIdx.x;
    const int tid = threadIdx.x;
    const unsigned char* ib = g_isb + b * TT;
    const unsigned char* pb = g_pad + b * TT;

    if (tid == 0) s_len = 0;
    __syncthreads();

    const int base = tid * 32;
    int lb = 0, lv = 0;
#pragma unroll 8
    for (int j = 0; j < 32; j++) {
        lb += ib[base + j];
        lv += (pb[base + j] == 0);
    }
    s_part[tid] = lb;
    atomicAdd(&s_len, lv);
    __syncthreads();

    if (tid == 0) {
        int run = 0;
        for (int i = 0; i < 256; i++) { int v = s_part[i]; s_part[i] = run; run += v; }
        s_nb = run;
    }
    __syncthreads();

    int cum = s_part[tid];
    int* gs = g_start + b * (TT + 1);
    for (int j = 0; j < 32; j++) {
        if (ib[base + j]) { cum++; gs[cum] = base + j; }
    }
    const int len = s_len, nb = s_nb;
    if (tid == 0) { gs[0] = 0; g_nb[b] = nb; g_len[b] = len; }

    if (has_pad_out) {
        int nv = (len > 0) ? nb + 1 : 0;
        for (int idx = tid; idx < TT; idx += 256)
            padout[b * TT + idx] = (idx >= nv) ? 1.0f : 0.0f;
    }
}

// ---------------- segment mean pooling (warp per segment slot) ----------------
__global__ void pool_kernel(const float* __restrict__ x, float* __restrict__ out) {
    int gw = (blockIdx.x * blockDim.x + threadIdx.x) >> 5;
    int lane = threadIdx.x & 31;
    int b = gw >> 13;
    int s = gw & (TT - 1);
    int nb = g_nb[b], len = g_len[b];
    int nv = (len > 0) ? nb + 1 : 0;

    float acc[8];
#pragma unroll
    for (int u = 0; u < 8; u++) acc[u] = 0.f;

    if (s < nv && s < TT) {
        const int* gs = g_start + b * (TT + 1);
        int st = gs[s];
        int en = (s == nb) ? len : gs[s + 1];
        int cnt = en - st;
        if (cnt > 0) {
            const float* xb = x + (((size_t)b * TT + st) << 8);
            for (int t = 0; t < cnt; t++) {
#pragma unroll
                for (int u = 0; u < 8; u++)
                    acc[u] += xb[(size_t)t * CC + lane + 32 * u];
            }
            float fc = (float)cnt;
#pragma unroll
            for (int u = 0; u < 8; u++) acc[u] /= fc;
        }
    }
    float* ob = out + (((size_t)b * TT + s) << 8);
#pragma unroll
    for (int u = 0; u < 8; u++) ob[lane + 32 * u] = acc[u];
}

// ---------------- launch ----------------
extern "C" void kernel_launch(void* const* d_in, const int* in_sizes, int n_in,
                              void* d_out, int out_size) {
    const float* x = (const float*)d_in[0];
    const unsigned char* pmask = (const unsigned char*)d_in[1];
    const float* w1 = (const float*)d_in[2];
    const float* b1 = (const float*)d_in[3];
    const float* w2 = (const float*)d_in[4];
    const float* b2 = (const float*)d_in[5];
    const float* w3 = (const float*)d_in[6];
    const float* b3 = (const float*)d_in[7];
    float* out = (float*)d_out;

    auto sym = [](const void* s) { void* p; cudaGetSymbolAddress(&p, s); return p; };
    __half* x0 = (__half*)sym(g_x0);
    __half* x1 = (__half*)sym(g_x1);
    __half* m0 = (__half*)sym(g_m0);
    __half* m1 = (__half*)sym(g_m1);
    __half* w1a = (__half*)sym(g_w1a);
    __half* w1b = (__half*)sym(g_w1b);
    __half* w2a = (__half*)sym(g_w2a);
    __half* w2b = (__half*)sym(g_w2b);
    float* lg = (float*)sym(g_logit);

    const size_t logits_elems = (size_t)BATCH * TT * CC;
    int has_pad_out = (out_size >= (int)(logits_elems + BATCH * TT)) ? 1 : 0;
    float* padout = out + logits_elems;

    cudaFuncSetAttribute(conv_mma<KW1, KW1 / 2, 1>,
                         cudaFuncAttributeMaxDynamicSharedMemorySize, SMEM_BYTES);
    cudaFuncSetAttribute(conv_mma<KW2, 1, 0>,
                         cudaFuncAttributeMaxDynamicSharedMemorySize, SMEM_BYTES);

    // 0) padding mask normalize + zero fused-logit buffer
    mask_reset_kernel<<<1, 1>>>();
    mask_detect_kernel<<<128, 256>>>(pmask);
    mask_normalize_kernel<<<(BATCH * TT + 255) / 256, 256>>>(pmask);
    zero_logits_kernel<<<(BATCH * TT * 2 + 255) / 256, 256>>>();

    // 1) weight prepack: w[h][c][k] -> wt[k][c][h] * WSCALE, 2 fp16 planes
    prepack_w_kernel<<<(256 * 256 * KW1 + 255) / 256, 256>>>(w1, w1a, w1b, KW1);
    prepack_w_kernel<<<(256 * 256 * KW2 + 255) / 256, 256>>>(w2, w2a, w2b, KW2);

    // 2) split x into 2 fp16 planes
    split_x_kernel<<<(int)((NELEM + 255) / 256), 256>>>(x, x0, x1, (int)NELEM);

    // 3) conv1 + relu -> h1 (2 fp16 planes)
    {
        dim3 grid(HH / 128, TT / 128, BATCH);
        conv_mma<KW1, KW1 / 2, 1><<<grid, 256, SMEM_BYTES>>>(
            x0, x1, w1a, w1b, b1, m0, m1, nullptr, nullptr);
    }
    // 4) conv2 + relu + fused conv3 partial logits
    {
        dim3 grid(HH / 128, TT / 128, BATCH);
        conv_mma<KW2, 1, 0><<<grid, 256, SMEM_BYTES>>>(
            m0, m1, w2a, w2b, b2, nullptr, nullptr, lg, w3);
    }
    // 5) boundary flags from logits
    boundary_kernel<<<(BATCH * TT + 255) / 256, 256>>>(b3);
    // 6) per-batch scan
    scan_kernel<<<BATCH, 256>>>(padout, has_pad_out);
    // 7) segment mean pooling
    pool_kernel<<<(BATCH * TT) / 8, 256>>>(x, out);
}